// round 13
// baseline (speedup 1.0000x reference)
#include <cuda_runtime.h>
#include <cuda_bf16.h>
#include <cstdint>

// Problem constants
#define BB 128
#define SS 512
#define UU 1024
#define TT 48

#define KCH 16            // floats per k-chunk (one k16 mma step)
#define NCH (UU / KCH)    // 64 chunks
#define STG 4             // cp.async pipeline stages
#define RSTRIDE 20        // smem row stride in floats (pad: 2-way max conflicts)

// Scratch (device globals — no runtime allocation)
__device__ float g_scores[BB * SS * TT];            // fp32 scores, 12.6 MB
// W pre-baked into mma.sync B-fragment layout:
// [s2 (32)][j (6)][lane (32)] uint4 = {b0,b1 of k-step 2*s2, b0,b1 of 2*s2+1}
__device__ __align__(16) uint4 g_Wfrag[32 * 6 * 32];

__device__ __forceinline__ uint32_t smem_u32(const void* p) {
    uint32_t a;
    asm("{ .reg .u64 t; cvta.to.shared.u64 t, %1; cvt.u32.u64 %0, t; }"
        : "=r"(a) : "l"(p));
    return a;
}
__device__ __forceinline__ uint32_t packbf(float2 f) {
    __nv_bfloat162 h = __float22bfloat162_rn(f);
    return *reinterpret_cast<uint32_t*>(&h);
}
__device__ __forceinline__ void mma16816(float d[4],
                                         uint32_t a0, uint32_t a1,
                                         uint32_t a2, uint32_t a3,
                                         uint32_t b0, uint32_t b1) {
    asm volatile(
        "mma.sync.aligned.m16n8k16.row.col.f32.bf16.bf16.f32 "
        "{%0,%1,%2,%3}, {%4,%5,%6,%7}, {%8,%9}, {%0,%1,%2,%3};"
        : "+f"(d[0]), "+f"(d[1]), "+f"(d[2]), "+f"(d[3])
        : "r"(a0), "r"(a1), "r"(a2), "r"(a3), "r"(b0), "r"(b1));
}
__device__ __forceinline__ void cp16(uint32_t dst, const void* src) {
    asm volatile("cp.async.cg.shared.global [%0], [%1], 16;"
                 :: "r"(dst), "l"(src) : "memory");
}
#define CP_COMMIT() asm volatile("cp.async.commit_group;" ::: "memory")
#define CP_WAIT(n)  asm volatile("cp.async.wait_group %0;" :: "n"(n) : "memory")

// ---------------------------------------------------------------------------
// One-shot: bake W [U][T] into B fragments (bf16) for mma.sync.
// ---------------------------------------------------------------------------
__global__ void wfrag_kernel(const float* __restrict__ W) {
    int idx = blockIdx.x * 256 + threadIdx.x;     // 0 .. 64*6*32-1
    if (idx >= 64 * 6 * 32) return;
    int lane = idx & 31;
    int j    = (idx >> 5) % 6;
    int s    = idx / (6 * 32);                    // k-step 0..63
    int c    = lane & 3;
    int n    = 8 * j + (lane >> 2);
    int k0   = 16 * s + 2 * c;
    uint32_t b0 = packbf(make_float2(W[(size_t)k0 * TT + n],
                                     W[(size_t)(k0 + 1) * TT + n]));
    uint32_t b1 = packbf(make_float2(W[(size_t)(k0 + 8) * TT + n],
                                     W[(size_t)(k0 + 9) * TT + n]));
    int s2 = s >> 1, h = s & 1;
    uint32_t* out = reinterpret_cast<uint32_t*>(&g_Wfrag[(s2 * 6 + j) * 32 + lane]);
    out[h * 2 + 0] = b0;
    out[h * 2 + 1] = b1;
}

// ---------------------------------------------------------------------------
// GEMM via mma.sync bf16 + cp.async 4-stage smem pipeline (R12-exact).
// 256 threads, 128 rows x 48 cols per CTA, grid 512.
// NOTE: launched TWICE this round (idempotent) to measure T_gemm = T13 - T12.
// ---------------------------------------------------------------------------
__global__ __launch_bounds__(256)
void gemm_mma(const float* __restrict__ H, const float* __restrict__ bias) {
    __shared__ __align__(16) float sA[STG * 128 * RSTRIDE];   // 40 KB

    const int tid  = threadIdx.x;
    const int w    = tid >> 5;
    const int lane = tid & 31;
    const int c    = lane & 3;       // 0..3
    const int g    = lane >> 2;      // 0..7

    const int crow  = tid >> 1;
    const int chalf = tid & 1;
    const float* gsrc = H + ((size_t)blockIdx.x * 128 + crow) * UU + chalf * 8;
    const uint32_t sbase = smem_u32(sA);
    const uint32_t cdst  = sbase + (crow * RSTRIDE + chalf * 8) * 4;

    const size_t m0 = (size_t)blockIdx.x * 128 + w * 16;
    const float* srow = sA + (w * 16 + g) * RSTRIDE + 2 * c;

    float2 bias2[6];
#pragma unroll
    for (int j = 0; j < 6; j++)
        bias2[j] = *reinterpret_cast<const float2*>(bias + 8 * j + 2 * c);

    float d[6][4];
#pragma unroll
    for (int j = 0; j < 6; j++)
#pragma unroll
        for (int i = 0; i < 4; i++) d[j][i] = 0.f;

    // prologue: stage chunks 0..2
#pragma unroll
    for (int ch = 0; ch < 3; ch++) {
        uint32_t dst = cdst + ch * (128 * RSTRIDE * 4);
        const float* src = gsrc + ch * KCH;
        cp16(dst, src);
        cp16(dst + 16, src + 4);
        CP_COMMIT();
    }

    for (int s2 = 0; s2 < 32; s2++) {
        // B fragments for both chunks of this s2 (one uint4 per j)
        uint4 bf[6];
        {
            const uint4* bp = g_Wfrag + (size_t)(s2 * 6) * 32 + lane;
#pragma unroll
            for (int j = 0; j < 6; j++) bf[j] = bp[j * 32];
        }

        // ---- chunk a = 2*s2 ----
        {
            const int ch = 2 * s2;
            if (ch < NCH - 2) { CP_WAIT(2); } else { CP_WAIT(0); }
            __syncthreads();
            if (ch + 3 < NCH) {
                uint32_t dst = cdst + ((ch + 3) & 3) * (128 * RSTRIDE * 4);
                const float* src = gsrc + (ch + 3) * KCH;
                cp16(dst, src);
                cp16(dst + 16, src + 4);
                CP_COMMIT();
            }
            const float* sp = srow + (ch & 3) * (128 * RSTRIDE);
            float2 f0 = *reinterpret_cast<const float2*>(sp);
            float2 f1 = *reinterpret_cast<const float2*>(sp + 8 * RSTRIDE);
            float2 f2 = *reinterpret_cast<const float2*>(sp + 8);
            float2 f3 = *reinterpret_cast<const float2*>(sp + 8 * RSTRIDE + 8);
            uint32_t a0 = packbf(f0), a1 = packbf(f1);
            uint32_t a2 = packbf(f2), a3 = packbf(f3);
#pragma unroll
            for (int j = 0; j < 6; j++)
                mma16816(d[j], a0, a1, a2, a3, bf[j].x, bf[j].y);
        }
        // ---- chunk b = 2*s2+1 ----
        {
            const int ch = 2 * s2 + 1;
            if (ch < NCH - 2) { CP_WAIT(2); } else { CP_WAIT(0); }
            __syncthreads();
            if (ch + 3 < NCH) {
                uint32_t dst = cdst + ((ch + 3) & 3) * (128 * RSTRIDE * 4);
                const float* src = gsrc + (ch + 3) * KCH;
                cp16(dst, src);
                cp16(dst + 16, src + 4);
                CP_COMMIT();
            }
            const float* sp = srow + (ch & 3) * (128 * RSTRIDE);
            float2 f0 = *reinterpret_cast<const float2*>(sp);
            float2 f1 = *reinterpret_cast<const float2*>(sp + 8 * RSTRIDE);
            float2 f2 = *reinterpret_cast<const float2*>(sp + 8);
            float2 f3 = *reinterpret_cast<const float2*>(sp + 8 * RSTRIDE + 8);
            uint32_t a0 = packbf(f0), a1 = packbf(f1);
            uint32_t a2 = packbf(f2), a3 = packbf(f3);
#pragma unroll
            for (int j = 0; j < 6; j++)
                mma16816(d[j], a0, a1, a2, a3, bf[j].z, bf[j].w);
        }
    }

    // Epilogue: D frag rows (g, g+8), cols 8j+2c..+1, add bias
    float* dst0 = g_scores + (m0 + g) * TT;
    float* dst1 = dst0 + 8 * TT;
#pragma unroll
    for (int j = 0; j < 6; j++) {
        *reinterpret_cast<float2*>(dst0 + 8 * j + 2 * c) =
            make_float2(d[j][0] + bias2[j].x, d[j][1] + bias2[j].y);
        *reinterpret_cast<float2*>(dst1 + 8 * j + 2 * c) =
            make_float2(d[j][2] + bias2[j].x, d[j][3] + bias2[j].y);
    }
}

// ---------------------------------------------------------------------------
// Fused scan + numerator (R12-exact).
// ---------------------------------------------------------------------------
__global__ void scan_kernel(const float* __restrict__ trans,
                            const float* __restrict__ startT,
                            const float* __restrict__ endT,
                            const int* __restrict__ tag,
                            const int* __restrict__ s_len,
                            float* __restrict__ out) {
    const int b = blockIdx.x;
    const int t = threadIdx.x;
    __shared__ __align__(16) float vbuf[2][64];
    __shared__ float red[TT];
    __shared__ float s_num;

    const int len = s_len[b];
    const float* sc = g_scores + (size_t)b * SS * TT;

    if (t < 64) {
        const bool act = t < TT;
        const int tc = act ? t : 0;

        float E[TT];
#pragma unroll
        for (int k = 0; k < TT; k++) {
            float e = __expf(trans[k * TT + tc]);
            E[k] = act ? e : 0.f;
        }

        vbuf[0][t] = act ? __expf(startT[tc] + sc[tc]) : 0.f;
        int Ce = 0;

        // pipeline: x1 = exp(emit[1]); eA = emit[2]; eB = emit[3]
        float x1 = __expf(sc[1 * TT + tc]);
        float eA = sc[2 * TT + tc];
        float eB = sc[3 * TT + tc];
        __syncthreads();                               // barrier 1

        int cur = 0;
        for (int s = 1; s < len; ++s) {
            float ex = x1;           // exp(emit[s])
            x1 = __expf(eA);         // exp(emit[s+1]) for next iter
            eA = eB;                 // emit[s+2]
            int sp = s + 3; if (sp > SS - 1) sp = SS - 1;
            eB = sc[sp * TT + tc];   // emit[s+3]: exp'd 2 iters from now

            const float4* vp = reinterpret_cast<const float4*>(vbuf[cur]);
            float4 q0 = vp[0], q1 = vp[1];

            int eb = (__float_as_int(q0.x) >> 23) & 0xff;
            Ce += eb - 127;
            float sx = __int_as_float((254 - eb) << 23) * ex;

            float a0 = q0.x * E[0], a1 = q0.y * E[1];
            float a2 = q0.z * E[2], a3 = q0.w * E[3];
            float a4 = q1.x * E[4], a5 = q1.y * E[5];
            float a6 = q1.z * E[6], a7 = q1.w * E[7];
#pragma unroll
            for (int j = 2; j < 12; j += 2) {
                float4 p1 = vp[j], p2 = vp[j + 1];
                a0 = fmaf(p1.x, E[4 * j + 0], a0);
                a1 = fmaf(p1.y, E[4 * j + 1], a1);
                a2 = fmaf(p1.z, E[4 * j + 2], a2);
                a3 = fmaf(p1.w, E[4 * j + 3], a3);
                a4 = fmaf(p2.x, E[4 * j + 4], a4);
                a5 = fmaf(p2.y, E[4 * j + 5], a5);
                a6 = fmaf(p2.z, E[4 * j + 6], a6);
                a7 = fmaf(p2.w, E[4 * j + 7], a7);
            }
            float dot = ((a0 + a1) + (a2 + a3)) + ((a4 + a5) + (a6 + a7));

            vbuf[cur ^ 1][t] = dot * sx;
            __syncthreads();                           // barriers 2..len
            cur ^= 1;
        }

        if (act) red[t] = vbuf[cur][t] * __expf(endT[t]);
        __syncthreads();                               // barrier len+1

        if (t == 0) {
            float ssum = 0.f;
#pragma unroll
            for (int k = 0; k < TT; k++) ssum += red[k];
            float logZ = (float)Ce * 0.6931471805599453f + __logf(ssum);
            out[b] = s_num - logZ;
        }
    } else {
        // warp 2: numerator, then spin len+1 barriers to match scan path
        const int l = t - 64;
        const int* tg = tag + b * SS;
        float local = 0.f;
        for (int s = l; s < len; s += 32) {
            int tc2 = tg[s];
            local += sc[s * TT + tc2];
            if (s >= 1) local += trans[tg[s - 1] * TT + tc2];
        }
        if (l == 0) local += startT[tg[0]] + endT[tg[len - 1]];
#pragma unroll
        for (int o = 16; o > 0; o >>= 1)
            local += __shfl_down_sync(0xffffffffu, local, o);
        if (l == 0) s_num = local;

        for (int i = 0; i < len + 1; i++) __syncthreads();
    }
}

// ---------------------------------------------------------------------------
// Launch. gemm_mma launched TWICE deliberately this round: it is idempotent
// (writes identical values), and T13 - T12 = T_gemm pins the gemm/scan split
// that ncu keeps refusing to show (it only ever profiles wfrag).
// ---------------------------------------------------------------------------
extern "C" void kernel_launch(void* const* d_in, const int* in_sizes, int n_in,
                              void* d_out, int out_size) {
    const float* H      = (const float*)d_in[0];
    const float* W      = (const float*)d_in[1];
    const float* bias   = (const float*)d_in[2];
    const float* startT = (const float*)d_in[3];
    const float* endT   = (const float*)d_in[4];
    const float* trans  = (const float*)d_in[5];
    const int*   tag    = (const int*)d_in[6];
    const int*   s_len  = (const int*)d_in[7];
    (void)in_sizes; (void)n_in; (void)out_size;
    float* out = (float*)d_out;

    wfrag_kernel<<<48, 256>>>(W);
    gemm_mma<<<(BB * SS) / 128, 256>>>(H, bias);
    gemm_mma<<<(BB * SS) / 128, 256>>>(H, bias);   // duplicate: measures T_gemm
    scan_kernel<<<BB, 96>>>(trans, startT, endT, tag, s_len, out);
}

// round 14
// speedup vs baseline: 1.5972x; 1.5972x over previous
#include <cuda_runtime.h>
#include <cuda_bf16.h>
#include <cstdint>

// Problem constants
#define BB 128
#define SS 512
#define UU 1024
#define TT 48

#define KCH 16            // floats per k-chunk (one k16 mma step)
#define NCH (UU / KCH)    // 64 chunks
#define STG 4             // cp.async pipeline stages
#define RSTRIDE 20        // smem row stride in floats (pad: 2-way max conflicts)

// Scratch (device globals — no runtime allocation)
__device__ float g_scores[BB * SS * TT];            // fp32 scores, 12.6 MB
// W pre-baked into mma.sync B-fragment layout:
// [s2 (32)][j (6)][lane (32)] uint4 = {b0,b1 of k-step 2*s2, b0,b1 of 2*s2+1}
__device__ __align__(16) uint4 g_Wfrag[32 * 6 * 32];

__device__ __forceinline__ uint32_t smem_u32(const void* p) {
    uint32_t a;
    asm("{ .reg .u64 t; cvta.to.shared.u64 t, %1; cvt.u32.u64 %0, t; }"
        : "=r"(a) : "l"(p));
    return a;
}
__device__ __forceinline__ uint32_t packbf(float2 f) {
    __nv_bfloat162 h = __float22bfloat162_rn(f);
    return *reinterpret_cast<uint32_t*>(&h);
}
__device__ __forceinline__ void mma16816(float d[4],
                                         uint32_t a0, uint32_t a1,
                                         uint32_t a2, uint32_t a3,
                                         uint32_t b0, uint32_t b1) {
    asm volatile(
        "mma.sync.aligned.m16n8k16.row.col.f32.bf16.bf16.f32 "
        "{%0,%1,%2,%3}, {%4,%5,%6,%7}, {%8,%9}, {%0,%1,%2,%3};"
        : "+f"(d[0]), "+f"(d[1]), "+f"(d[2]), "+f"(d[3])
        : "r"(a0), "r"(a1), "r"(a2), "r"(a3), "r"(b0), "r"(b1));
}
__device__ __forceinline__ void cp16(uint32_t dst, const void* src) {
    asm volatile("cp.async.cg.shared.global [%0], [%1], 16;"
                 :: "r"(dst), "l"(src) : "memory");
}
#define CP_COMMIT() asm volatile("cp.async.commit_group;" ::: "memory")
#define CP_WAIT(n)  asm volatile("cp.async.wait_group %0;" :: "n"(n) : "memory")

// 48-element dot of E[] (regs) with vec (smem, float4-aligned), 8 accumulators
__device__ __forceinline__ float dot48(const float* E, const float* vec,
                                       float& first) {
    const float4* vp = reinterpret_cast<const float4*>(vec);
    float4 q0 = vp[0], q1 = vp[1];
    first = q0.x;
    float a0 = q0.x * E[0], a1 = q0.y * E[1];
    float a2 = q0.z * E[2], a3 = q0.w * E[3];
    float a4 = q1.x * E[4], a5 = q1.y * E[5];
    float a6 = q1.z * E[6], a7 = q1.w * E[7];
#pragma unroll
    for (int j = 2; j < 12; j += 2) {
        float4 p1 = vp[j], p2 = vp[j + 1];
        a0 = fmaf(p1.x, E[4 * j + 0], a0);
        a1 = fmaf(p1.y, E[4 * j + 1], a1);
        a2 = fmaf(p1.z, E[4 * j + 2], a2);
        a3 = fmaf(p1.w, E[4 * j + 3], a3);
        a4 = fmaf(p2.x, E[4 * j + 4], a4);
        a5 = fmaf(p2.y, E[4 * j + 5], a5);
        a6 = fmaf(p2.z, E[4 * j + 6], a6);
        a7 = fmaf(p2.w, E[4 * j + 7], a7);
    }
    return ((a0 + a1) + (a2 + a3)) + ((a4 + a5) + (a6 + a7));
}

// ---------------------------------------------------------------------------
// One-shot: bake W [U][T] into B fragments (bf16) for mma.sync.
// ---------------------------------------------------------------------------
__global__ void wfrag_kernel(const float* __restrict__ W) {
    int idx = blockIdx.x * 256 + threadIdx.x;     // 0 .. 64*6*32-1
    if (idx >= 64 * 6 * 32) return;
    int lane = idx & 31;
    int j    = (idx >> 5) % 6;
    int s    = idx / (6 * 32);                    // k-step 0..63
    int c    = lane & 3;
    int n    = 8 * j + (lane >> 2);
    int k0   = 16 * s + 2 * c;
    uint32_t b0 = packbf(make_float2(W[(size_t)k0 * TT + n],
                                     W[(size_t)(k0 + 1) * TT + n]));
    uint32_t b1 = packbf(make_float2(W[(size_t)(k0 + 8) * TT + n],
                                     W[(size_t)(k0 + 9) * TT + n]));
    int s2 = s >> 1, h = s & 1;
    uint32_t* out = reinterpret_cast<uint32_t*>(&g_Wfrag[(s2 * 6 + j) * 32 + lane]);
    out[h * 2 + 0] = b0;
    out[h * 2 + 1] = b1;
}

// ---------------------------------------------------------------------------
// GEMM via mma.sync bf16 + cp.async 4-stage smem pipeline (R12-exact, 75us).
// ---------------------------------------------------------------------------
__global__ __launch_bounds__(256)
void gemm_mma(const float* __restrict__ H, const float* __restrict__ bias) {
    __shared__ __align__(16) float sA[STG * 128 * RSTRIDE];   // 40 KB

    const int tid  = threadIdx.x;
    const int w    = tid >> 5;
    const int lane = tid & 31;
    const int c    = lane & 3;
    const int g    = lane >> 2;

    const int crow  = tid >> 1;
    const int chalf = tid & 1;
    const float* gsrc = H + ((size_t)blockIdx.x * 128 + crow) * UU + chalf * 8;
    const uint32_t sbase = smem_u32(sA);
    const uint32_t cdst  = sbase + (crow * RSTRIDE + chalf * 8) * 4;

    const size_t m0 = (size_t)blockIdx.x * 128 + w * 16;
    const float* srow = sA + (w * 16 + g) * RSTRIDE + 2 * c;

    float2 bias2[6];
#pragma unroll
    for (int j = 0; j < 6; j++)
        bias2[j] = *reinterpret_cast<const float2*>(bias + 8 * j + 2 * c);

    float d[6][4];
#pragma unroll
    for (int j = 0; j < 6; j++)
#pragma unroll
        for (int i = 0; i < 4; i++) d[j][i] = 0.f;

#pragma unroll
    for (int ch = 0; ch < 3; ch++) {
        uint32_t dst = cdst + ch * (128 * RSTRIDE * 4);
        const float* src = gsrc + ch * KCH;
        cp16(dst, src);
        cp16(dst + 16, src + 4);
        CP_COMMIT();
    }

    for (int s2 = 0; s2 < 32; s2++) {
        uint4 bf[6];
        {
            const uint4* bp = g_Wfrag + (size_t)(s2 * 6) * 32 + lane;
#pragma unroll
            for (int j = 0; j < 6; j++) bf[j] = bp[j * 32];
        }
        {
            const int ch = 2 * s2;
            if (ch < NCH - 2) { CP_WAIT(2); } else { CP_WAIT(0); }
            __syncthreads();
            if (ch + 3 < NCH) {
                uint32_t dst = cdst + ((ch + 3) & 3) * (128 * RSTRIDE * 4);
                const float* src = gsrc + (ch + 3) * KCH;
                cp16(dst, src);
                cp16(dst + 16, src + 4);
                CP_COMMIT();
            }
            const float* sp = srow + (ch & 3) * (128 * RSTRIDE);
            float2 f0 = *reinterpret_cast<const float2*>(sp);
            float2 f1 = *reinterpret_cast<const float2*>(sp + 8 * RSTRIDE);
            float2 f2 = *reinterpret_cast<const float2*>(sp + 8);
            float2 f3 = *reinterpret_cast<const float2*>(sp + 8 * RSTRIDE + 8);
            uint32_t a0 = packbf(f0), a1 = packbf(f1);
            uint32_t a2 = packbf(f2), a3 = packbf(f3);
#pragma unroll
            for (int j = 0; j < 6; j++)
                mma16816(d[j], a0, a1, a2, a3, bf[j].x, bf[j].y);
        }
        {
            const int ch = 2 * s2 + 1;
            if (ch < NCH - 2) { CP_WAIT(2); } else { CP_WAIT(0); }
            __syncthreads();
            if (ch + 3 < NCH) {
                uint32_t dst = cdst + ((ch + 3) & 3) * (128 * RSTRIDE * 4);
                const float* src = gsrc + (ch + 3) * KCH;
                cp16(dst, src);
                cp16(dst + 16, src + 4);
                CP_COMMIT();
            }
            const float* sp = srow + (ch & 3) * (128 * RSTRIDE);
            float2 f0 = *reinterpret_cast<const float2*>(sp);
            float2 f1 = *reinterpret_cast<const float2*>(sp + 8 * RSTRIDE);
            float2 f2 = *reinterpret_cast<const float2*>(sp + 8);
            float2 f3 = *reinterpret_cast<const float2*>(sp + 8 * RSTRIDE + 8);
            uint32_t a0 = packbf(f0), a1 = packbf(f1);
            uint32_t a2 = packbf(f2), a3 = packbf(f3);
#pragma unroll
            for (int j = 0; j < 6; j++)
                mma16816(d[j], a0, a1, a2, a3, bf[j].z, bf[j].w);
        }
    }

    float* dst0 = g_scores + (m0 + g) * TT;
    float* dst1 = dst0 + 8 * TT;
#pragma unroll
    for (int j = 0; j < 6; j++) {
        *reinterpret_cast<float2*>(dst0 + 8 * j + 2 * c) =
            make_float2(d[j][0] + bias2[j].x, d[j][1] + bias2[j].y);
        *reinterpret_cast<float2*>(dst1 + 8 * j + 2 * c) =
            make_float2(d[j][2] + bias2[j].x, d[j][3] + bias2[j].y);
    }
}

// ---------------------------------------------------------------------------
// BIDIRECTIONAL fused scan + numerator. 160 threads/block:
//   threads 0-63  : forward  alpha scan, m = (len-1)/2 steps (E columns).
//   threads 64-127: backward beta  scan, K = len-1-m steps  (E rows).
//       w_s = x_s ∘ b_s ;  b_{s-1} = E·w_s ;  last step (s==m) skips the x.
//   threads 128-159: numerator, then spins exactly K+2 barriers.
// Serial barrier count: K ≈ len/2 (was len-1). Same exponent-bit renorm on
// both directions (vectors strictly positive); exponents summed at the end.
// logZ = (Cf+Cb)·ln2 + log(sum_t alpha_m[t]·beta_m[t]);  out = num - logZ.
// ---------------------------------------------------------------------------
__global__ void scan_kernel(const float* __restrict__ trans,
                            const float* __restrict__ startT,
                            const float* __restrict__ endT,
                            const int* __restrict__ tag,
                            const int* __restrict__ s_len,
                            float* __restrict__ out) {
    const int b = blockIdx.x;
    const int t = threadIdx.x;
    __shared__ __align__(16) float fbuf[2][64];   // forward alpha (linear)
    __shared__ __align__(16) float bbuf[2][64];   // backward w / b (linear)
    __shared__ float redf[TT];
    __shared__ float redb[TT];
    __shared__ float s_num;
    __shared__ int   s_CeB;

    const int len = s_len[b];
    const int m   = (len - 1) >> 1;      // meeting point
    const int K   = len - 1 - m;         // loop length (K >= m, K-m in {0,1})
    const float* sc = g_scores + (size_t)b * SS * TT;

    if (t < 64) {
        // ---------------- FORWARD group: state t ----------------
        const bool act = t < TT;
        const int tc = act ? t : 0;

        float E[TT];
#pragma unroll
        for (int k = 0; k < TT; k++) {
            float e = __expf(trans[k * TT + tc]);   // column t
            E[k] = act ? e : 0.f;
        }
        fbuf[0][t] = act ? __expf(startT[tc] + sc[tc]) : 0.f;
        int Ce = 0;

        float x1 = __expf(sc[1 * TT + tc]);
        float eA = sc[2 * TT + tc];
        float eB = sc[3 * TT + tc];
        __syncthreads();                               // barrier 1 (init)

        int cur = 0;
        for (int i = 0; i < K; ++i) {
            if (i < m) {
                const int s = i + 1;
                float ex = x1;
                x1 = __expf(eA); eA = eB;
                int sp = s + 3; if (sp > SS - 1) sp = SS - 1;
                eB = sc[sp * TT + tc];

                float v0;
                float dot = dot48(E, fbuf[cur], v0);

                int eb = (__float_as_int(v0) >> 23) & 0xff;
                Ce += eb - 127;
                float sx = __int_as_float((254 - eb) << 23) * ex;

                fbuf[cur ^ 1][t] = dot * sx;
                cur ^= 1;
            }
            __syncthreads();                           // barriers 2..K+1
        }
        if (act) redf[t] = fbuf[cur][t];               // alpha_m (renormed)
        __syncthreads();                               // barrier K+2

        if (t == 0) {
            float ssum = 0.f;
#pragma unroll
            for (int k = 0; k < TT; k++) ssum += redf[k] * redb[k];
            float logZ = (float)(Ce + s_CeB) * 0.6931471805599453f + __logf(ssum);
            out[b] = s_num - logZ;
        }
    } else if (t < 128) {
        // ---------------- BACKWARD group: state u ----------------
        const int u = t - 64;
        const bool act = u < TT;
        const int uc = act ? u : 0;

        float E[TT];
#pragma unroll
        for (int k = 0; k < TT; k++) {
            float e = __expf(trans[uc * TT + k]);   // row u
            E[k] = act ? e : 0.f;
        }
        // init w_{len-1} = exp(emit_{len-1} + end)
        bbuf[0][u] = act ? __expf(sc[(size_t)(len - 1) * TT + uc] + endT[uc]) : 0.f;
        int Ce = 0;

        int p1 = len - 2; if (p1 < 0) p1 = 0;
        int p2 = len - 3; if (p2 < 0) p2 = 0;
        int p3 = len - 4; if (p3 < 0) p3 = 0;
        float x1 = __expf(sc[(size_t)p1 * TT + uc]);
        float eA = sc[(size_t)p2 * TT + uc];
        float eB = sc[(size_t)p3 * TT + uc];
        __syncthreads();                               // barrier 1 (init)

        int cur = 0;
        for (int i = 0; i < K; ++i) {
            const int s = len - 2 - i;                 // s: len-2 .. m
            float ex = x1;
            x1 = __expf(eA); eA = eB;
            int sp = s - 3; if (sp < 0) sp = 0;
            eB = sc[(size_t)sp * TT + uc];

            float w0;
            float dot = dot48(E, bbuf[cur], w0);       // b_s[u] = E_row_u · w_{s+1}

            int eb = (__float_as_int(w0) >> 23) & 0xff;
            Ce += eb - 127;
            float scale = __int_as_float((254 - eb) << 23);

            float val = (s > m) ? (dot * scale * ex)   // w_s = x_s ∘ b_s
                                : (dot * scale);       // final b_m (no x)
            bbuf[cur ^ 1][u] = val;
            cur ^= 1;
            __syncthreads();                           // barriers 2..K+1
        }
        if (act) redb[u] = K ? bbuf[cur][u]            // b_m (renormed)
                             : __expf(endT[uc]);       // len==1: beta = exp(end)
        if (u == 0) s_CeB = Ce;
        __syncthreads();                               // barrier K+2
    } else {
        // ---------------- numerator warp ----------------
        const int l = t - 128;
        const int* tg = tag + b * SS;
        float local = 0.f;
        for (int s = l; s < len; s += 32) {
            int tc2 = tg[s];
            local += sc[s * TT + tc2];
            if (s >= 1) local += trans[tg[s - 1] * TT + tc2];
        }
        if (l == 0) local += startT[tg[0]] + endT[tg[len - 1]];
#pragma unroll
        for (int o = 16; o > 0; o >>= 1)
            local += __shfl_down_sync(0xffffffffu, local, o);
        if (l == 0) s_num = local;

        for (int i = 0; i < K + 2; i++) __syncthreads();
    }
}

// ---------------------------------------------------------------------------
// Launch. Inputs: H, W, b, start_transitions, end_transitions, transitions,
// tag(int32), s_len(int32), w_mask (unused: mask == s < s_len).
// ---------------------------------------------------------------------------
extern "C" void kernel_launch(void* const* d_in, const int* in_sizes, int n_in,
                              void* d_out, int out_size) {
    const float* H      = (const float*)d_in[0];
    const float* W      = (const float*)d_in[1];
    const float* bias   = (const float*)d_in[2];
    const float* startT = (const float*)d_in[3];
    const float* endT   = (const float*)d_in[4];
    const float* trans  = (const float*)d_in[5];
    const int*   tag    = (const int*)d_in[6];
    const int*   s_len  = (const int*)d_in[7];
    (void)in_sizes; (void)n_in; (void)out_size;
    float* out = (float*)d_out;

    wfrag_kernel<<<48, 256>>>(W);
    gemm_mma<<<(BB * SS) / 128, 256>>>(H, bias);
    scan_kernel<<<BB, 160>>>(trans, startT, endT, tag, s_len, out);
}